// round 4
// baseline (speedup 1.0000x reference)
#include <cuda_runtime.h>
#include <cstdint>

// ---------------------------------------------------------------------------
// Problem dims
// ---------------------------------------------------------------------------
#define T_STEPS 256
#define BATCH   128
#define N_INP   784
#define N_HID   512
#define N_OUT   128
#define M_TOTAL (T_STEPS * BATCH)   // 32768
#define NWORDS1 25                  // ceil(784/32)
#define MSTRIDE 32                  // padded words per input-mask row
#define HWORDS  16                  // 512/32 hidden-mask words per row

// ---------------------------------------------------------------------------
// Scratch globals
// ---------------------------------------------------------------------------
__device__ __align__(128) float    g_wt1[N_INP * N_HID];            // 1.6 MB  w_hidden^T
__device__ __align__(128) float    g_wt2[N_HID * N_OUT];            // 256 KB  w_out^T
__device__ __align__(128) uint32_t g_m1[(size_t)M_TOTAL * MSTRIDE]; // 4 MB    input spike bitmask
__device__ __align__(128) uint32_t g_shb[(size_t)M_TOTAL * HWORDS]; // 2 MB    hidden spike bitmask
__device__ __align__(128) float    g_co0[(size_t)M_TOTAL * N_OUT];  // 16 MB   c_o partial (k-slice 0)
__device__ __align__(128) float    g_co1[(size_t)M_TOTAL * N_OUT];  // 16 MB   c_o partial (k-slice 1)

// ---------------------------------------------------------------------------
// Prep: transpose weights
// ---------------------------------------------------------------------------
__global__ void prep_wt1_kernel(const float* __restrict__ wh, float* __restrict__ wt1)
{
    int idx = blockIdx.x * blockDim.x + threadIdx.x;       // k*512 + u
    if (idx >= N_INP * N_HID) return;
    int k = idx >> 9;            // /512
    int u = idx & 511;
    wt1[idx] = __ldg(wh + (size_t)u * N_INP + k);
}

__global__ void prep_wt2_kernel(const float* __restrict__ wo, float* __restrict__ wt2)
{
    int idx = blockIdx.x * blockDim.x + threadIdx.x;       // k*128 + o
    if (idx >= N_HID * N_OUT) return;
    int k = idx >> 7;
    int o = idx & 127;
    wt2[idx] = __ldg(wo + (size_t)o * N_HID + k);
}

// ---------------------------------------------------------------------------
// Prep: input spikes f32 -> bitmask (25 words used, padded to 32)
// ---------------------------------------------------------------------------
__global__ void prep_masks_kernel(const float* __restrict__ sp, uint32_t* __restrict__ m1)
{
    int gid = blockIdx.x * blockDim.x + threadIdx.x;       // row*32 + w
    if (gid >= M_TOTAL * MSTRIDE) return;
    int row = gid >> 5;
    int w   = gid & 31;
    uint32_t bits = 0;
    if (w < NWORDS1) {
        const float* p = sp + (size_t)row * N_INP + w * 32;
        int lim = N_INP - w * 32; if (lim > 32) lim = 32;
        if (lim == 32) {
            const float4* q = (const float4*)p;
#pragma unroll
            for (int j = 0; j < 8; j++) {
                float4 f = q[j];
                bits |= (f.x > 0.5f ? 1u : 0u) << (j * 4 + 0);
                bits |= (f.y > 0.5f ? 1u : 0u) << (j * 4 + 1);
                bits |= (f.z > 0.5f ? 1u : 0u) << (j * 4 + 2);
                bits |= (f.w > 0.5f ? 1u : 0u) << (j * 4 + 3);
            }
        } else {
            for (int j = 0; j < lim; j++)
                bits |= (p[j] > 0.5f ? 1u : 0u) << j;
        }
    }
    m1[gid] = bits;
}

// ---------------------------------------------------------------------------
// F1: fused sparse GEMM1 + LIF.
// Grid (8 chunks of 64 hidden units, 16 btiles of 8 batches). 256 threads.
// Warp = one batch; lane owns units (u, u+32) of the chunk.
// SMEM: per-chunk weight slab as float2[784][32] = 200704 B.
// Walks t sequentially, keeping (v,i) in registers; c_h never hits DRAM.
// Emits hidden spikes as bitmask words (chunk c owns words 2c, 2c+1).
// ---------------------------------------------------------------------------
__global__ __launch_bounds__(256, 1)
void f1_kernel(const float* __restrict__ wt1, const uint32_t* __restrict__ m1,
               uint32_t* __restrict__ shb)
{
    extern __shared__ float2 sw[];                         // [784][32]
    const int tid   = threadIdx.x;
    const int wid   = tid >> 5;
    const int lane  = tid & 31;
    const int chunk = blockIdx.x;                          // 0..7
    const int ubase = chunk * 64;

    // load weight slab: sw[k][l] = (wt1[k][ubase+l], wt1[k][ubase+32+l])
    for (int idx = tid; idx < N_INP * 32; idx += 256) {
        int k = idx >> 5, l = idx & 31;
        sw[idx] = make_float2(wt1[(size_t)k * N_HID + ubase + l],
                              wt1[(size_t)k * N_HID + ubase + 32 + l]);
    }
    __syncthreads();

    const int b = blockIdx.y * 8 + wid;                    // global batch
    const float Am = (float)(1e-6 * (1.0 / 6e-6));
    const float Cd = (float)(1.0 - 1e-6 * (1.0 / 6e-6));
    float v0 = 0.f, i0 = 0.f, v1 = 0.f, i1 = 0.f;

    uint32_t mw = (lane < NWORDS1) ? m1[(size_t)b * MSTRIDE + lane] : 0u;   // t = 0

    for (int t = 0; t < T_STEPS; t++) {
        uint32_t mw_next = 0u;
        if (t + 1 < T_STEPS && lane < NWORDS1)
            mw_next = m1[((size_t)(t + 1) * BATCH + b) * MSTRIDE + lane];

        float a0 = 0.f, a1 = 0.f;
#pragma unroll
        for (int wi = 0; wi < NWORDS1; wi++) {
            uint32_t m = __shfl_sync(0xffffffffu, mw, wi);
            int kb = wi * 32;
            while (m) {
                int kk = kb + __ffs(m) - 1;
                m &= m - 1;
                float2 w2 = sw[kk * 32 + lane];
                a0 += w2.x;
                a1 += w2.y;
            }
        }

        // LIF update (reference op order, verified in R1)
        v0 = v0 + Am * (i0 - v0);  i0 = i0 * Cd + a0;
        v1 = v1 + Am * (i1 - v1);  i1 = i1 * Cd + a1;
        bool z0 = (v0 - 1.0f) > 0.0f;
        bool z1 = (v1 - 1.0f) > 0.0f;
        uint32_t bb0 = __ballot_sync(0xffffffffu, z0);
        uint32_t bb1 = __ballot_sync(0xffffffffu, z1);
        size_t rb = ((size_t)t * BATCH + b) * HWORDS + chunk * 2;
        if (lane == 0) shb[rb]     = bb0;
        if (lane == 1) shb[rb + 1] = bb1;
        if (z0) v0 = 0.0f;
        if (z1) v1 = 0.0f;

        mw = mw_next;
    }
}

// ---------------------------------------------------------------------------
// F2: sparse GEMM2 partial sums from hidden bitmask.
// Grid x: (chunk 0..1 of 64 outs) * (kslice 0..1 of 256 hidden); y: 32 btiles of 4.
// 128 threads; warp = batch, lane owns outs (o, o+32). SMEM float2[256][32]=64KB.
// Writes partial c_o for its k-slice (summed in LI kernel).
// ---------------------------------------------------------------------------
__global__ __launch_bounds__(128, 1)
void f2_kernel(const float* __restrict__ wt2, const uint32_t* __restrict__ shb,
               float* __restrict__ co0, float* __restrict__ co1)
{
    extern __shared__ float2 sw2[];                        // [256][32]
    const int tid   = threadIdx.x;
    const int wid   = tid >> 5;
    const int lane  = tid & 31;
    const int chunk = blockIdx.x >> 1;                     // 0..1
    const int ks    = blockIdx.x & 1;                      // 0..1
    const int obase = chunk * 64;
    float* __restrict__ co = ks ? co1 : co0;

    for (int idx = tid; idx < 256 * 32; idx += 128) {
        int k = idx >> 5, l = idx & 31;
        int kg = ks * 256 + k;
        sw2[idx] = make_float2(wt2[(size_t)kg * N_OUT + obase + l],
                               wt2[(size_t)kg * N_OUT + obase + 32 + l]);
    }
    __syncthreads();

    const int b = blockIdx.y * 4 + wid;
    uint32_t mw = (lane < 8) ? shb[(size_t)b * HWORDS + ks * 8 + lane] : 0u;

    for (int t = 0; t < T_STEPS; t++) {
        uint32_t mw_next = 0u;
        if (t + 1 < T_STEPS && lane < 8)
            mw_next = shb[((size_t)(t + 1) * BATCH + b) * HWORDS + ks * 8 + lane];

        float a0 = 0.f, a1 = 0.f;
#pragma unroll
        for (int wi = 0; wi < 8; wi++) {
            uint32_t m = __shfl_sync(0xffffffffu, mw, wi);
            int kb = wi * 32;
            while (m) {
                int kk = kb + __ffs(m) - 1;
                m &= m - 1;
                float2 w2 = sw2[kk * 32 + lane];
                a0 += w2.x;
                a1 += w2.y;
            }
        }

        size_t o = ((size_t)t * BATCH + b) * N_OUT + obase;
        co[o + lane]      = a0;
        co[o + 32 + lane] = a1;

        mw = mw_next;
    }
}

// ---------------------------------------------------------------------------
// LI readout scan: x = co0 + co1; emits membrane trace.
// ---------------------------------------------------------------------------
__global__ void li_kernel(const float* __restrict__ co0, const float* __restrict__ co1,
                          float* __restrict__ out)
{
    const int tid = blockIdx.x * blockDim.x + threadIdx.x;   // b*128 + o
    const float Am = (float)(1e-6 * (1.0 / 6e-6));
    const float Cd = (float)(1.0 - 1e-6 * (1.0 / 6e-6));
    float v = 0.0f, cur = 0.0f;
    const int stride = BATCH * N_OUT;                        // 16384

    for (int t0 = 0; t0 < T_STEPS; t0 += 16) {
        float x[16];
#pragma unroll
        for (int u = 0; u < 16; u++) {
            size_t idx = (size_t)(t0 + u) * stride + tid;
            x[u] = co0[idx] + co1[idx];
        }
#pragma unroll
        for (int u = 0; u < 16; u++) {
            v = v + Am * (cur - v);
            cur = cur * Cd + x[u];
            out[(size_t)(t0 + u) * stride + tid] = v;
        }
    }
}

// ---------------------------------------------------------------------------
// Launch: preps -> F1 (GEMM1+LIF fused) -> F2 (GEMM2 partials) -> LI
// ---------------------------------------------------------------------------
extern "C" void kernel_launch(void* const* d_in, const int* in_sizes, int n_in,
                              void* d_out, int out_size)
{
    const float* spikes = (const float*)d_in[0];   // [256,128,784] f32 (binary)
    const float* wh     = (const float*)d_in[1];   // [512,784] f32
    const float* wo     = (const float*)d_in[2];   // [128,512] f32
    float*       out    = (float*)d_out;           // [256,128,128] f32

    float *wt1, *wt2, *co0, *co1;
    uint32_t *m1, *shb;
    cudaGetSymbolAddress((void**)&wt1, g_wt1);
    cudaGetSymbolAddress((void**)&wt2, g_wt2);
    cudaGetSymbolAddress((void**)&m1,  g_m1);
    cudaGetSymbolAddress((void**)&shb, g_shb);
    cudaGetSymbolAddress((void**)&co0, g_co0);
    cudaGetSymbolAddress((void**)&co1, g_co1);

    constexpr int SMEM_F1 = N_INP * 32 * sizeof(float2);   // 200704
    constexpr int SMEM_F2 = 256 * 32 * sizeof(float2);     // 65536
    cudaFuncSetAttribute((const void*)f1_kernel, cudaFuncAttributeMaxDynamicSharedMemorySize, SMEM_F1);
    cudaFuncSetAttribute((const void*)f2_kernel, cudaFuncAttributeMaxDynamicSharedMemorySize, SMEM_F2);

    // 1) preps
    prep_wt1_kernel<<<(N_INP * N_HID + 255) / 256, 256>>>(wh, wt1);
    prep_wt2_kernel<<<(N_HID * N_OUT + 255) / 256, 256>>>(wo, wt2);
    prep_masks_kernel<<<(M_TOTAL * MSTRIDE + 255) / 256, 256>>>(spikes, m1);

    // 2) fused sparse GEMM1 + LIF -> hidden spike bitmask
    {
        dim3 grid(N_HID / 64, BATCH / 8);                  // (8, 16) = 128 CTAs
        f1_kernel<<<grid, 256, SMEM_F1>>>(wt1, m1, shb);
    }

    // 3) sparse GEMM2 partials (2 chunks x 2 k-slices x 32 btiles)
    {
        dim3 grid(4, BATCH / 4);                           // (4, 32) = 128 CTAs
        f2_kernel<<<grid, 128, SMEM_F2>>>(wt2, shb, co0, co1);
    }

    // 4) LI readout scan
    li_kernel<<<(BATCH * N_OUT) / 256, 256>>>(co0, co1, out);
}

// round 6
// speedup vs baseline: 3.9536x; 3.9536x over previous
#include <cuda_runtime.h>
#include <cstdint>

// ---------------------------------------------------------------------------
// Problem dims
// ---------------------------------------------------------------------------
#define T_STEPS 256
#define BATCH   128
#define N_INP   784
#define N_HID   512
#define N_OUT   128
#define M_TOTAL (T_STEPS * BATCH)   // 32768
#define L1STRIDE 160                // u16 slots per input list row (max actives ~130)
#define L2STRIDE 512                // u16 slots per hidden list row (hard cap)
#define HWORDS   16                 // 512/32 hidden-mask words per row

// ---------------------------------------------------------------------------
// Scratch globals
// ---------------------------------------------------------------------------
__device__ __align__(128) float    g_wt1[N_INP * N_HID];              // 1.6 MB  w_hidden^T
__device__ __align__(128) float    g_wt2[N_HID * N_OUT];              // 256 KB  w_out^T
__device__ __align__(128) uint16_t g_list1[(size_t)M_TOTAL * L1STRIDE]; // 10.5 MB
__device__ __align__(128) int      g_cnt1[M_TOTAL];
__device__ __align__(128) uint32_t g_shb[(size_t)M_TOTAL * HWORDS];   // 2 MB hidden bitmask
__device__ __align__(128) uint16_t g_list2[(size_t)M_TOTAL * L2STRIDE]; // 33.5 MB
__device__ __align__(128) int      g_cnt2[M_TOTAL];
__device__ __align__(128) float    g_co[(size_t)M_TOTAL * N_OUT];     // 16 MB

// ---------------------------------------------------------------------------
// Weight transposes
// ---------------------------------------------------------------------------
__global__ void prep_wt1_kernel(const float* __restrict__ wh, float* __restrict__ wt1)
{
    int idx = blockIdx.x * blockDim.x + threadIdx.x;     // k*512 + u
    if (idx >= N_INP * N_HID) return;
    int k = idx >> 9, u = idx & 511;
    wt1[idx] = __ldg(wh + (size_t)u * N_INP + k);
}
__global__ void prep_wt2_kernel(const float* __restrict__ wo, float* __restrict__ wt2)
{
    int idx = blockIdx.x * blockDim.x + threadIdx.x;     // k*128 + o
    if (idx >= N_HID * N_OUT) return;
    int k = idx >> 7, o = idx & 127;
    wt2[idx] = __ldg(wo + (size_t)o * N_HID + k);
}

// ---------------------------------------------------------------------------
// Build active-index list per (t,b) row directly from f32 spikes.
// One warp per row. Pads count up to multiple of 8 with index N_INP (zero row).
// ---------------------------------------------------------------------------
__global__ void build_list1_kernel(const float* __restrict__ sp,
                                   uint16_t* __restrict__ list, int* __restrict__ cnts)
{
    const int wid  = threadIdx.x >> 5;
    const int lane = threadIdx.x & 31;
    const int row  = blockIdx.x * 8 + wid;               // 4096 blocks x 8 warps

    uint32_t w = 0;
    if (lane < 24) {
        const float4* p = (const float4*)(sp + (size_t)row * N_INP + lane * 32);
#pragma unroll
        for (int j = 0; j < 8; j++) {
            float4 f = p[j];
            w |= (uint32_t)(f.x > 0.5f) << (j * 4 + 0);
            w |= (uint32_t)(f.y > 0.5f) << (j * 4 + 1);
            w |= (uint32_t)(f.z > 0.5f) << (j * 4 + 2);
            w |= (uint32_t)(f.w > 0.5f) << (j * 4 + 3);
        }
    } else if (lane == 24) {
        const float4* p = (const float4*)(sp + (size_t)row * N_INP + 768);
#pragma unroll
        for (int j = 0; j < 4; j++) {                    // inputs 768..783
            float4 f = p[j];
            w |= (uint32_t)(f.x > 0.5f) << (j * 4 + 0);
            w |= (uint32_t)(f.y > 0.5f) << (j * 4 + 1);
            w |= (uint32_t)(f.z > 0.5f) << (j * 4 + 2);
            w |= (uint32_t)(f.w > 0.5f) << (j * 4 + 3);
        }
    }

    int c = __popc(w);
    int incl = c;
#pragma unroll
    for (int d = 1; d < 32; d <<= 1) {
        int n = __shfl_up_sync(0xffffffffu, incl, d);
        if (lane >= d) incl += n;
    }
    int total = __shfl_sync(0xffffffffu, incl, 31);
    int p0 = incl - c;

    uint16_t* lp = list + (size_t)row * L1STRIDE;
    uint32_t m = w;
    int kb = lane * 32;
    while (m) {
        int k = kb + __ffs(m) - 1;
        m &= m - 1;
        lp[p0++] = (uint16_t)k;
    }
    int rt = (total + 7) & ~7;
    if (lane < rt - total) lp[total + lane] = (uint16_t)N_INP;   // pad -> zero weight row
    if (lane == 0) cnts[row] = total;
}

// ---------------------------------------------------------------------------
// Build hidden active-index list from the ballot bitmask (16 words/row).
// ---------------------------------------------------------------------------
__global__ void build_list2_kernel(const uint32_t* __restrict__ mask,
                                   uint16_t* __restrict__ list, int* __restrict__ cnts)
{
    const int wid  = threadIdx.x >> 5;
    const int lane = threadIdx.x & 31;
    const int row  = blockIdx.x * 8 + wid;

    uint32_t w = (lane < HWORDS) ? mask[(size_t)row * HWORDS + lane] : 0u;
    int c = __popc(w);
    int incl = c;
#pragma unroll
    for (int d = 1; d < 32; d <<= 1) {
        int n = __shfl_up_sync(0xffffffffu, incl, d);
        if (lane >= d) incl += n;
    }
    int total = __shfl_sync(0xffffffffu, incl, 31);
    int p0 = incl - c;

    uint16_t* lp = list + (size_t)row * L2STRIDE;
    uint32_t m = w;
    int kb = lane * 32;
    while (m) {
        int k = kb + __ffs(m) - 1;
        m &= m - 1;
        lp[p0++] = (uint16_t)k;
    }
    int rt = (total + 7) & ~7;
    if (lane < rt - total) lp[total + lane] = (uint16_t)N_HID;
    if (lane == 0) cnts[row] = total;
}

// ---------------------------------------------------------------------------
// F1: fused sparse GEMM1 + LIF.
// Grid (16 chunks of 32 units, 16 btiles of 8). 256 thr; warp = batch, lane = unit.
// SMEM: weight slab float[785][32] (row 784 = zeros for padding indices).
// Inner loop: uint4 of 8 u16 indices (prefetched 1 ahead), 8 LDS + 8 FADD.
// ---------------------------------------------------------------------------
__global__ __launch_bounds__(256)
void f1_kernel(const float* __restrict__ wt1, const uint16_t* __restrict__ list,
               const int* __restrict__ cnts, uint32_t* __restrict__ shb)
{
    extern __shared__ float sw[];                        // (784+1)*32
    const int tid   = threadIdx.x;
    const int wid   = tid >> 5;
    const int lane  = tid & 31;
    const int chunk = blockIdx.x;                        // 0..15
    const int ub    = chunk * 32;

    for (int i = tid; i < (N_INP + 1) * 32; i += 256) {
        int k = i >> 5, l = i & 31;
        sw[i] = (k < N_INP) ? wt1[(size_t)k * N_HID + ub + l] : 0.0f;
    }
    __syncthreads();

    const int b = blockIdx.y * 8 + wid;
    const float Am = (float)(1e-6 * (1.0 / 6e-6));
    const float Cd = (float)(1.0 - 1e-6 * (1.0 / 6e-6));
    float v = 0.0f, cur = 0.0f;

    for (int t = 0; t < T_STEPS; t++) {
        const int row = t * BATCH + b;
        const int cnt = (cnts[row] + 7) & ~7;
        const uint4* lp = (const uint4*)(list + (size_t)row * L1STRIDE);

        float a = 0.0f;
        uint4 pk = lp[0];
        for (int j = 0; j < cnt; j += 8) {
            uint4 nx = (j + 8 < cnt) ? lp[(j >> 3) + 1] : pk;
            a += sw[(pk.x & 0xffffu) * 32 + lane];
            a += sw[(pk.x >> 16) * 32 + lane];
            a += sw[(pk.y & 0xffffu) * 32 + lane];
            a += sw[(pk.y >> 16) * 32 + lane];
            a += sw[(pk.z & 0xffffu) * 32 + lane];
            a += sw[(pk.z >> 16) * 32 + lane];
            a += sw[(pk.w & 0xffffu) * 32 + lane];
            a += sw[(pk.w >> 16) * 32 + lane];
            pk = nx;
        }

        // LIF (reference op order, verified R1)
        v = v + Am * (cur - v);
        cur = cur * Cd + a;
        bool z = (v - 1.0f) > 0.0f;
        uint32_t bb = __ballot_sync(0xffffffffu, z);
        if (lane == 0) shb[(size_t)row * HWORDS + chunk] = bb;
        if (z) v = 0.0f;
    }
}

// ---------------------------------------------------------------------------
// F2: sparse GEMM2 from hidden lists. No recurrence -> t-sliced x4.
// Grid x = chunk(4 of 32 outs) + 4*tslice(4 of 64 steps); y = 16 btiles of 8.
// ---------------------------------------------------------------------------
__global__ __launch_bounds__(256)
void f2_kernel(const float* __restrict__ wt2, const uint16_t* __restrict__ list,
               const int* __restrict__ cnts, float* __restrict__ co)
{
    extern __shared__ float sw[];                        // (512+1)*32
    const int tid   = threadIdx.x;
    const int wid   = tid >> 5;
    const int lane  = tid & 31;
    const int chunk = blockIdx.x & 3;
    const int ts    = blockIdx.x >> 2;
    const int ob    = chunk * 32;

    for (int i = tid; i < (N_HID + 1) * 32; i += 256) {
        int k = i >> 5, l = i & 31;
        sw[i] = (k < N_HID) ? wt2[(size_t)k * N_OUT + ob + l] : 0.0f;
    }
    __syncthreads();

    const int b = blockIdx.y * 8 + wid;
    const int t0 = ts * (T_STEPS / 4), t1 = t0 + T_STEPS / 4;

    for (int t = t0; t < t1; t++) {
        const int row = t * BATCH + b;
        const int cnt = (cnts[row] + 7) & ~7;
        const uint4* lp = (const uint4*)(list + (size_t)row * L2STRIDE);

        float a = 0.0f;
        uint4 pk = lp[0];
        for (int j = 0; j < cnt; j += 8) {
            uint4 nx = (j + 8 < cnt) ? lp[(j >> 3) + 1] : pk;
            a += sw[(pk.x & 0xffffu) * 32 + lane];
            a += sw[(pk.x >> 16) * 32 + lane];
            a += sw[(pk.y & 0xffffu) * 32 + lane];
            a += sw[(pk.y >> 16) * 32 + lane];
            a += sw[(pk.z & 0xffffu) * 32 + lane];
            a += sw[(pk.z >> 16) * 32 + lane];
            a += sw[(pk.w & 0xffffu) * 32 + lane];
            a += sw[(pk.w >> 16) * 32 + lane];
            pk = nx;
        }
        co[(size_t)row * N_OUT + ob + lane] = a;
    }
}

// ---------------------------------------------------------------------------
// LI readout scan
// ---------------------------------------------------------------------------
__global__ void li_kernel(const float* __restrict__ co, float* __restrict__ out)
{
    const int tid = blockIdx.x * blockDim.x + threadIdx.x;   // b*128 + o
    const float Am = (float)(1e-6 * (1.0 / 6e-6));
    const float Cd = (float)(1.0 - 1e-6 * (1.0 / 6e-6));
    float v = 0.0f, cur = 0.0f;
    const int stride = BATCH * N_OUT;

    for (int t0 = 0; t0 < T_STEPS; t0 += 16) {
        float x[16];
#pragma unroll
        for (int u = 0; u < 16; u++)
            x[u] = co[(size_t)(t0 + u) * stride + tid];
#pragma unroll
        for (int u = 0; u < 16; u++) {
            v = v + Am * (cur - v);
            cur = cur * Cd + x[u];
            out[(size_t)(t0 + u) * stride + tid] = v;
        }
    }
}

// ---------------------------------------------------------------------------
// Launch
// ---------------------------------------------------------------------------
extern "C" void kernel_launch(void* const* d_in, const int* in_sizes, int n_in,
                              void* d_out, int out_size)
{
    const float* spikes = (const float*)d_in[0];
    const float* wh     = (const float*)d_in[1];
    const float* wo     = (const float*)d_in[2];
    float*       out    = (float*)d_out;

    float *wt1, *wt2, *co;
    uint16_t *l1, *l2;
    int *c1, *c2;
    uint32_t *shb;
    cudaGetSymbolAddress((void**)&wt1, g_wt1);
    cudaGetSymbolAddress((void**)&wt2, g_wt2);
    cudaGetSymbolAddress((void**)&l1,  g_list1);
    cudaGetSymbolAddress((void**)&c1,  g_cnt1);
    cudaGetSymbolAddress((void**)&shb, g_shb);
    cudaGetSymbolAddress((void**)&l2,  g_list2);
    cudaGetSymbolAddress((void**)&c2,  g_cnt2);
    cudaGetSymbolAddress((void**)&co,  g_co);

    constexpr int SW1 = (N_INP + 1) * 32 * sizeof(float);   // 100480
    constexpr int SW2 = (N_HID + 1) * 32 * sizeof(float);   //  65664
    cudaFuncSetAttribute((const void*)f1_kernel, cudaFuncAttributeMaxDynamicSharedMemorySize, SW1);
    cudaFuncSetAttribute((const void*)f2_kernel, cudaFuncAttributeMaxDynamicSharedMemorySize, SW2);

    // preps
    prep_wt1_kernel<<<(N_INP * N_HID + 255) / 256, 256>>>(wh, wt1);
    prep_wt2_kernel<<<(N_HID * N_OUT + 255) / 256, 256>>>(wo, wt2);
    build_list1_kernel<<<M_TOTAL / 8, 256>>>(spikes, l1, c1);

    // fused sparse GEMM1 + LIF
    f1_kernel<<<dim3(16, 16), 256, SW1>>>(wt1, l1, c1, shb);

    // hidden lists + sparse GEMM2 (t-sliced)
    build_list2_kernel<<<M_TOTAL / 8, 256>>>(shb, l2, c2);
    f2_kernel<<<dim3(16, 16), 256, SW2>>>(wt2, l2, c2, co);

    // LI readout
    li_kernel<<<(BATCH * N_OUT) / 256, 256>>>(co, out);
}